// round 3
// baseline (speedup 1.0000x reference)
#include <cuda_runtime.h>
#include <cuda_bf16.h>

#define IN_C  256
#define OUT_C 128
#define MAX_N 100352   // >= 100000

// Scratch for H = X @ W^T (N x OUT_C). Device global: no allocation allowed.
__device__ float g_H[(size_t)MAX_N * OUT_C];

// ---------------------------------------------------------------------------
// GEMM: H[n,o] = sum_k X[n,k] * W[o,k]   (NT, K = 256)
// BM=128, BN=128(=OUT_C), BK=16, 256 threads, 8x8 register tile.
// ---------------------------------------------------------------------------
#define BM 128
#define BN 128
#define BK 16
#define TM 8
#define TN 8

__global__ __launch_bounds__(256, 2)
void gemm_nt_kernel(const float* __restrict__ X,
                    const float* __restrict__ W,
                    int N)
{
    __shared__ float As[BK][BM];   // As[k][m]
    __shared__ float Bs[BK][BN];   // Bs[k][n]

    const int tid = threadIdx.x;
    const int tx  = tid & 15;
    const int ty  = tid >> 4;
    const int block_row = blockIdx.x * BM;

    float acc[TM][TN];
#pragma unroll
    for (int i = 0; i < TM; i++)
#pragma unroll
        for (int j = 0; j < TN; j++) acc[i][j] = 0.0f;

    for (int k0 = 0; k0 < IN_C; k0 += BK) {
#pragma unroll
        for (int it = 0; it < 2; it++) {
            int idx = tid + it * 256;       // 0..511
            int row = idx >> 2;             // 0..127
            int k4  = (idx & 3) << 2;       // 0,4,8,12
            float4 va = make_float4(0.f, 0.f, 0.f, 0.f);
            int grow = block_row + row;
            if (grow < N)
                va = *(const float4*)(X + (size_t)grow * IN_C + k0 + k4);
            As[k4 + 0][row] = va.x;
            As[k4 + 1][row] = va.y;
            As[k4 + 2][row] = va.z;
            As[k4 + 3][row] = va.w;
        }
#pragma unroll
        for (int it = 0; it < 2; it++) {
            int idx = tid + it * 256;
            int row = idx >> 2;             // out channel 0..127
            int k4  = (idx & 3) << 2;
            float4 vb = *(const float4*)(W + (size_t)row * IN_C + k0 + k4);
            Bs[k4 + 0][row] = vb.x;
            Bs[k4 + 1][row] = vb.y;
            Bs[k4 + 2][row] = vb.z;
            Bs[k4 + 3][row] = vb.w;
        }
        __syncthreads();

#pragma unroll
        for (int k = 0; k < BK; k++) {
            float a[TM], b[TN];
#pragma unroll
            for (int i = 0; i < TM; i++) a[i] = As[k][ty * TM + i];
#pragma unroll
            for (int j = 0; j < TN; j++) b[j] = Bs[k][tx * TN + j];
#pragma unroll
            for (int i = 0; i < TM; i++)
#pragma unroll
                for (int j = 0; j < TN; j++)
                    acc[i][j] += a[i] * b[j];
        }
        __syncthreads();
    }

#pragma unroll
    for (int i = 0; i < TM; i++) {
        int grow = block_row + ty * TM + i;
        if (grow < N) {
            float* dst = g_H + (size_t)grow * OUT_C + tx * TN;
            *(float4*)(dst + 0) = make_float4(acc[i][0], acc[i][1], acc[i][2], acc[i][3]);
            *(float4*)(dst + 4) = make_float4(acc[i][4], acc[i][5], acc[i][6], acc[i][7]);
        }
    }
}

// ---------------------------------------------------------------------------
// SpMM: out[r,:] += v * H[c,:] over row-sorted COO edges.
// One WARP per chunk of WEPW edges; lane owns 4 contiguous channels (float4).
// Edge metadata loaded 32-wide, broadcast via shfl. Register accumulation
// with flush-on-row-change. Interior rows (exclusively owned by this warp,
// since rows are sorted) flush with a plain STG.128; only the first row of
// the warp's range and the final flush (both possibly shared with the
// neighboring warps) use atomics.
// ---------------------------------------------------------------------------
#define WEPW 512            // edges per warp
#define SPMM_WARPS 8        // warps per block

__global__ __launch_bounds__(SPMM_WARPS * 32)
void spmm_kernel(const int*   __restrict__ rows,
                 const int*   __restrict__ cols,
                 const float* __restrict__ vals,
                 float*       __restrict__ out,
                 int E)
{
    const int warp_id = blockIdx.x * SPMM_WARPS + (threadIdx.x >> 5);
    const int lane    = threadIdx.x & 31;
    const int e0      = warp_id * WEPW;
    if (e0 >= E) return;

    const int n_edges = min(WEPW, E - e0);

    float4 acc = make_float4(0.f, 0.f, 0.f, 0.f);
    const int first_row = rows[e0];   // may be shared with the previous warp
    int cur = first_row;

    for (int base = 0; base < n_edges; base += 32) {
        const int e  = e0 + base + lane;
        int   r = 0, c = 0;
        float v = 0.0f;
        if (e < E) { r = rows[e]; c = cols[e]; v = vals[e]; }
        const int cnt = min(32, n_edges - base);

        for (int j = 0; j < cnt; j++) {
            const int   rj = __shfl_sync(0xFFFFFFFFu, r, j);
            const int   cj = __shfl_sync(0xFFFFFFFFu, c, j);
            const float vj = __shfl_sync(0xFFFFFFFFu, v, j);

            if (rj != cur) {
                float* dst = out + (size_t)cur * OUT_C + lane * 4;
                if (cur == first_row) {
                    atomicAdd(dst + 0, acc.x);
                    atomicAdd(dst + 1, acc.y);
                    atomicAdd(dst + 2, acc.z);
                    atomicAdd(dst + 3, acc.w);
                } else {
                    *(float4*)dst = acc;   // interior row: exclusive owner
                }
                acc = make_float4(0.f, 0.f, 0.f, 0.f);
                cur = rj;
            }
            const float4 h = *(const float4*)(g_H + (size_t)cj * OUT_C + lane * 4);
            acc.x += vj * h.x;
            acc.y += vj * h.y;
            acc.z += vj * h.z;
            acc.w += vj * h.w;
        }
    }

    // Final flush: row may continue into the next warp (or be first_row) -> atomic.
    float* dst = out + (size_t)cur * OUT_C + lane * 4;
    atomicAdd(dst + 0, acc.x);
    atomicAdd(dst + 1, acc.y);
    atomicAdd(dst + 2, acc.z);
    atomicAdd(dst + 3, acc.w);
}

// ---------------------------------------------------------------------------
// Inputs (metadata order): X [N*256] f32, W [128*256] f32,
//                          A_rows [E] i32, A_cols [E] i32, A_vals [E] f32
// Output: f32 [N*128]
// ---------------------------------------------------------------------------
extern "C" void kernel_launch(void* const* d_in, const int* in_sizes, int n_in,
                              void* d_out, int out_size)
{
    const float* X    = (const float*)d_in[0];
    const float* W    = (const float*)d_in[1];
    const int*   rows = (const int*)  d_in[2];
    const int*   cols = (const int*)  d_in[3];
    const float* vals = (const float*)d_in[4];
    float*       out  = (float*)d_out;

    const int N = in_sizes[0] / IN_C;
    const int E = in_sizes[2];

    cudaMemsetAsync(out, 0, (size_t)out_size * sizeof(float));

    const int gemm_blocks = (N + BM - 1) / BM;
    gemm_nt_kernel<<<gemm_blocks, 256>>>(X, W, N);

    const int total_warps = (E + WEPW - 1) / WEPW;
    const int spmm_blocks = (total_warps + SPMM_WARPS - 1) / SPMM_WARPS;
    spmm_kernel<<<spmm_blocks, SPMM_WARPS * 32>>>(rows, cols, vals, out, E);
}

// round 9
// speedup vs baseline: 2.1379x; 2.1379x over previous
#include <cuda_runtime.h>
#include <cuda_bf16.h>
#include <cstdint>

#define IN_C  256
#define OUT_C 128
#define MAX_N 100352   // >= 100000

// Scratch for H = X @ W^T (N x OUT_C). Device global: no allocation allowed.
__device__ float g_H[(size_t)MAX_N * OUT_C];

// ---------------------------------------------------------------------------
// tf32 helpers
// ---------------------------------------------------------------------------
__device__ __forceinline__ uint32_t f2tf32(float x) {
    uint32_t u;
    asm("cvt.rna.tf32.f32 %0, %1;" : "=r"(u) : "f"(x));
    return u;
}

__device__ __forceinline__ void mma_tf32(float* d, const uint32_t* a, const uint32_t* b) {
    asm volatile(
        "mma.sync.aligned.m16n8k8.row.col.f32.tf32.tf32.f32 "
        "{%0,%1,%2,%3}, {%4,%5,%6,%7}, {%8,%9}, {%0,%1,%2,%3};\n"
        : "+f"(d[0]), "+f"(d[1]), "+f"(d[2]), "+f"(d[3])
        : "r"(a[0]), "r"(a[1]), "r"(a[2]), "r"(a[3]),
          "r"(b[0]), "r"(b[1]));
}

// ---------------------------------------------------------------------------
// GEMM (tf32 tensor): H[m,n] = sum_k X[m,k] * W[n,k]
// CTA tile 128x128, BK=32, 256 threads = 8 warps, warp tile 32x64.
// As/Bs row-major [128][LDK], LDK=36 (== 4 mod 32): conflict-free uint4
// stores AND conflict-free fragment loads (bank = 4*gp + tg, bijective).
// ---------------------------------------------------------------------------
#define LDK 36

__global__ __launch_bounds__(256, 2)
void gemm_tf32_kernel(const float* __restrict__ X,
                      const float* __restrict__ W,
                      int N)
{
    __shared__ uint32_t As[128][LDK];   // As[m][k]  (tf32 bits)
    __shared__ uint32_t Bs[128][LDK];   // Bs[n][k]  (tf32 bits)

    const int tid  = threadIdx.x;
    const int lane = tid & 31;
    const int wid  = tid >> 5;
    const int wm   = wid & 3;          // 0..3
    const int wn   = wid >> 2;         // 0..1
    const int m_base = wm * 32;
    const int n_base = wn * 64;
    const int tg = lane & 3;           // thread-in-group
    const int gp = lane >> 2;          // group id
    const int block_row = blockIdx.x * 128;

    float d[2][8][4];
#pragma unroll
    for (int i = 0; i < 2; i++)
#pragma unroll
        for (int j = 0; j < 8; j++)
#pragma unroll
            for (int q = 0; q < 4; q++) d[i][j][q] = 0.0f;

    for (int k0 = 0; k0 < IN_C; k0 += 32) {
        // ---- load + convert tiles: 128 rows x 32 k each ----
#pragma unroll
        for (int it = 0; it < 4; it++) {
            int idx = tid + it * 256;        // 0..1023
            int row = idx >> 3;              // 0..127
            int k4  = (idx & 7) << 2;        // 0,4,...,28

            float4 va = make_float4(0.f, 0.f, 0.f, 0.f);
            int grow = block_row + row;
            if (grow < N)
                va = *(const float4*)(X + (size_t)grow * IN_C + k0 + k4);
            uint4 ua = make_uint4(f2tf32(va.x), f2tf32(va.y), f2tf32(va.z), f2tf32(va.w));
            *(uint4*)&As[row][k4] = ua;

            float4 vb = *(const float4*)(W + (size_t)row * IN_C + k0 + k4);
            uint4 ub = make_uint4(f2tf32(vb.x), f2tf32(vb.y), f2tf32(vb.z), f2tf32(vb.w));
            *(uint4*)&Bs[row][k4] = ub;
        }
        __syncthreads();

        // ---- compute: 4 k8-steps ----
#pragma unroll
        for (int ks = 0; ks < 32; ks += 8) {
            uint32_t a[2][4];
#pragma unroll
            for (int i = 0; i < 2; i++) {
                int m = m_base + i * 16 + gp;
                a[i][0] = As[m    ][ks + tg    ];
                a[i][1] = As[m + 8][ks + tg    ];
                a[i][2] = As[m    ][ks + tg + 4];
                a[i][3] = As[m + 8][ks + tg + 4];
            }
            uint32_t b[8][2];
#pragma unroll
            for (int j = 0; j < 8; j++) {
                int n = n_base + j * 8 + gp;
                b[j][0] = Bs[n][ks + tg    ];
                b[j][1] = Bs[n][ks + tg + 4];
            }
#pragma unroll
            for (int i = 0; i < 2; i++)
#pragma unroll
                for (int j = 0; j < 8; j++)
                    mma_tf32(d[i][j], a[i], b[j]);
        }
        __syncthreads();
    }

    // ---- epilogue: scatter fragments to g_H ----
#pragma unroll
    for (int i = 0; i < 2; i++) {
        int mrow = block_row + m_base + i * 16 + gp;
#pragma unroll
        for (int j = 0; j < 8; j++) {
            int n = n_base + j * 8 + tg * 2;
            if (mrow < N)
                *(float2*)(g_H + (size_t)mrow * OUT_C + n) =
                    make_float2(d[i][j][0], d[i][j][1]);
            if (mrow + 8 < N)
                *(float2*)(g_H + (size_t)(mrow + 8) * OUT_C + n) =
                    make_float2(d[i][j][2], d[i][j][3]);
        }
    }
}

// ---------------------------------------------------------------------------
// SpMM: out[r,:] += v * H[c,:] over row-sorted COO edges.
// One WARP per chunk of WEPW edges; lane owns 4 channels (float4).
// Inner loop processes 4 edges per step: all 4 gathers issued before the
// branchy accumulate -> MLP=4 (R3 ncu showed latency-bound, MLP~1).
// Interior rows flush with plain STG.128 (exclusive owner, rows sorted);
// first row of range + final flush use atomics (may span warps).
// ---------------------------------------------------------------------------
#define WEPW 256            // edges per warp
#define SPMM_WARPS 8

__global__ __launch_bounds__(SPMM_WARPS * 32)
void spmm_kernel(const int*   __restrict__ rows,
                 const int*   __restrict__ cols,
                 const float* __restrict__ vals,
                 float*       __restrict__ out,
                 int E)
{
    const int warp_id = blockIdx.x * SPMM_WARPS + (threadIdx.x >> 5);
    const int lane    = threadIdx.x & 31;
    const int e0      = warp_id * WEPW;
    if (e0 >= E) return;

    const int n_edges = min(WEPW, E - e0);

    float4 acc = make_float4(0.f, 0.f, 0.f, 0.f);
    const int first_row = rows[e0];
    int cur = first_row;

    for (int base = 0; base < n_edges; base += 32) {
        const int e = e0 + base + lane;
        int   r = 0, c = 0;
        float v = 0.0f;
        if (e < E) { r = rows[e]; c = cols[e]; v = vals[e]; }
        const int cnt = min(32, n_edges - base);

        int j = 0;
        for (; j + 4 <= cnt; j += 4) {
            int   rj[4], cj[4];
            float vj[4];
#pragma unroll
            for (int q = 0; q < 4; q++) {
                rj[q] = __shfl_sync(0xFFFFFFFFu, r, j + q);
                cj[q] = __shfl_sync(0xFFFFFFFFu, c, j + q);
                vj[q] = __shfl_sync(0xFFFFFFFFu, v, j + q);
            }
            float4 h[4];
#pragma unroll
            for (int q = 0; q < 4; q++)
                h[q] = *(const float4*)(g_H + (size_t)cj[q] * OUT_C + lane * 4);
#pragma unroll
            for (int q = 0; q < 4; q++) {
                if (rj[q] != cur) {
                    float* dst = out + (size_t)cur * OUT_C + lane * 4;
                    if (cur == first_row) {
                        atomicAdd(dst + 0, acc.x);
                        atomicAdd(dst + 1, acc.y);
                        atomicAdd(dst + 2, acc.z);
                        atomicAdd(dst + 3, acc.w);
                    } else {
                        *(float4*)dst = acc;
                    }
                    acc = make_float4(0.f, 0.f, 0.f, 0.f);
                    cur = rj[q];
                }
                acc.x += vj[q] * h[q].x;
                acc.y += vj[q] * h[q].y;
                acc.z += vj[q] * h[q].z;
                acc.w += vj[q] * h[q].w;
            }
        }
        for (; j < cnt; j++) {
            const int   rj = __shfl_sync(0xFFFFFFFFu, r, j);
            const int   cj = __shfl_sync(0xFFFFFFFFu, c, j);
            const float vj = __shfl_sync(0xFFFFFFFFu, v, j);
            if (rj != cur) {
                float* dst = out + (size_t)cur * OUT_C + lane * 4;
                if (cur == first_row) {
                    atomicAdd(dst + 0, acc.x);
                    atomicAdd(dst + 1, acc.y);
                    atomicAdd(dst + 2, acc.z);
                    atomicAdd(dst + 3, acc.w);
                } else {
                    *(float4*)dst = acc;
                }
                acc = make_float4(0.f, 0.f, 0.f, 0.f);
                cur = rj;
            }
            const float4 h = *(const float4*)(g_H + (size_t)cj * OUT_C + lane * 4);
            acc.x += vj * h.x;
            acc.y += vj * h.y;
            acc.z += vj * h.z;
            acc.w += vj * h.w;
        }
    }

    float* dst = out + (size_t)cur * OUT_C + lane * 4;
    atomicAdd(dst + 0, acc.x);
    atomicAdd(dst + 1, acc.y);
    atomicAdd(dst + 2, acc.z);
    atomicAdd(dst + 3, acc.w);
}

// ---------------------------------------------------------------------------
// Inputs (metadata order): X [N*256] f32, W [128*256] f32,
//                          A_rows [E] i32, A_cols [E] i32, A_vals [E] f32
// Output: f32 [N*128]
// ---------------------------------------------------------------------------
extern "C" void kernel_launch(void* const* d_in, const int* in_sizes, int n_in,
                              void* d_out, int out_size)
{
    const float* X    = (const float*)d_in[0];
    const float* W    = (const float*)d_in[1];
    const int*   rows = (const int*)  d_in[2];
    const int*   cols = (const int*)  d_in[3];
    const float* vals = (const float*)d_in[4];
    float*       out  = (float*)d_out;

    const int N = in_sizes[0] / IN_C;
    const int E = in_sizes[2];

    cudaMemsetAsync(out, 0, (size_t)out_size * sizeof(float));

    const int gemm_blocks = (N + 127) / 128;
    gemm_tf32_kernel<<<gemm_blocks, 256>>>(X, W, N);

    const int total_warps = (E + WEPW - 1) / WEPW;
    const int spmm_blocks = (total_warps + SPMM_WARPS - 1) / SPMM_WARPS;
    spmm_kernel<<<spmm_blocks, SPMM_WARPS * 32>>>(rows, cols, vals, out, E);
}